// round 16
// baseline (speedup 1.0000x reference)
#include <cuda_runtime.h>
#include <cuda_fp16.h>

#define B 32
#define R 5
#define C 100
#define C4 25     // c-quarter
#define N 101
#define NPAD 104
#define H 128
#define E 5
#define F 13      // 8 + R
#define TN 8      // nodes per einsum tile
#define NT 13     // ceil(N / TN)
#define TG 16     // nodes per gemm tile

// ---------------- scratch (device globals; no allocations allowed) ----------
__device__ __half g_pemb[(size_t)B * N * C * H];       // 82.7 MB, fp16
__device__ float  g_pres[(size_t)B * C * N];           // presence [B,C,N]
__device__ float  g_fx  [(size_t)B * N * H];           // fx1 then fx2
__device__ float  g_ua  [(size_t)B * N * H];           // state ping
__device__ float  g_ub  [(size_t)B * N * H];           // state pong
__device__ float  g_l   [4 * (size_t)B * NPAD * H];    // einsum partials (4 c-quarters)

extern __shared__ char smraw[];

__device__ __forceinline__ __half2 tanh2_fast(__half2 x) {
    unsigned xi = *(unsigned*)&x, yi;
    asm("tanh.approx.f16x2 %0, %1;" : "=r"(yi) : "r"(xi));
    return *(__half2*)&yi;
}

// ---------------- features: x -> fx1, u = relu(fx1 + bl1) -------------------
__global__ void k_features(const float* __restrict__ ap, const float* __restrict__ act,
                           const float* __restrict__ xa, const float* __restrict__ xb,
                           const float* __restrict__ coord, const float* __restrict__ avail,
                           const float* __restrict__ wx1, const float* __restrict__ bx1,
                           const float* __restrict__ bl1)
{
    int b = blockIdx.x / N, n = blockIdx.x % N;
    __shared__ float xs[F];
    int tid = threadIdx.x;
    if (tid < 5) {
        float s = 0.f;
        #pragma unroll
        for (int r = 0; r < R; r++) {
            int idx = (b * R + r) * N + n;
            float a = ap[idx] + act[idx];
            s = fmaf(a, xa[idx * R + tid], s);
        }
        xs[tid] = s;
    } else if (tid < 10) {
        xs[tid] = xb[(b * N + n) * 5 + tid - 5];
    } else if (tid < 12) {
        xs[tid] = coord[(b * N + n) * 2 + tid - 10];
    } else if (tid == 12) {
        xs[12] = avail[b * N + n];
    }
    __syncthreads();
    int h = tid;
    float acc = bx1[h];
    #pragma unroll
    for (int k = 0; k < F; k++) acc = fmaf(xs[k], wx1[k * H + h], acc);
    int o = (b * N + n) * H + h;
    g_fx[o] = acc;
    g_ua[o] = fmaxf(acc + bl1[h], 0.f);
}

// ---------------- presence head: softmax over n per (b,c) -------------------
__global__ void k_presence(const float* __restrict__ edge, const float* __restrict__ avail,
                           const float* __restrict__ w1p, const float* __restrict__ b1p,
                           const float* __restrict__ w2p, const float* __restrict__ b2p)
{
    int b = blockIdx.x / C, c = blockIdx.x % C;
    __shared__ float w1s[E * H], b1s[H], w2s[H], lg[N], red[H];
    int tid = threadIdx.x;
    for (int i = tid; i < E * H; i += H) w1s[i] = w1p[i];
    b1s[tid] = b1p[tid];
    w2s[tid] = w2p[tid];
    __syncthreads();

    float lgv = -3.4e38f;
    if (tid < N) {
        int n = tid;
        const float* e5 = edge + ((size_t)(b * C + c) * N + n) * E;
        float e0 = e5[0], e1 = e5[1], e2 = e5[2], e3 = e5[3], e4 = e5[4];
        float s = 0.f;
        #pragma unroll 4
        for (int h = 0; h < H; h++) {
            float a = b1s[h];
            a = fmaf(e0, w1s[h], a);
            a = fmaf(e1, w1s[H + h], a);
            a = fmaf(e2, w1s[2 * H + h], a);
            a = fmaf(e3, w1s[3 * H + h], a);
            a = fmaf(e4, w1s[4 * H + h], a);
            s = fmaf(fmaxf(a, 0.f), w2s[h], s);
        }
        s = s + b2p[0];                  // TAU = 1
        float m = avail[b * N + n];
        if (n == c || n == N - 1) m = 0.f;
        lgv = s * m - (1.f - m) * 1e10f;
        lg[n] = lgv;
    }
    red[tid] = lgv;
    __syncthreads();
    for (int s2 = 64; s2 > 0; s2 >>= 1) {
        if (tid < s2) red[tid] = fmaxf(red[tid], red[tid + s2]);
        __syncthreads();
    }
    float mx = red[0];
    __syncthreads();
    float p = 0.f;
    if (tid < N) p = __expf(lg[tid] - mx);
    red[tid] = p;
    __syncthreads();
    for (int s2 = 64; s2 > 0; s2 >>= 1) {
        if (tid < s2) red[tid] += red[tid + s2];
        __syncthreads();
    }
    float inv = 1.f / red[0];
    if (tid < N) {
        float availc = avail[b * N + c];
        g_pres[(size_t)(b * C + c) * N + tid] = availc * p * inv;
    }
}

// ---------------- fused: build pemb + einsum + GEMM -> u_out ----------------
// grid = B*26 (4 nodes per CTA), block 512. One full MP iteration + pemb build.
__global__ void __launch_bounds__(512) k_pemb_fused(
    const float* __restrict__ edge, const float* __restrict__ we,
    const float* __restrict__ be, const float* __restrict__ wl,
    const float* __restrict__ bl,
    const float* __restrict__ u_in, float* __restrict__ u_out)
{
    int b = blockIdx.x / 26, g = blockIdx.x % 26;
    char* sm = smraw;
    __half*  ush = (__half*)sm;                          // C*128 half  = 25600 B
    float*   es  = (float*)(sm + 25600);                 // 4*C*E       =  8000 B
    float*   ps  = (float*)(sm + 33600);                 // 4*C         =  1600 B
    float2*  wes = (float2*)(sm + 35200);                // E*64 float2 =  2560 B
    float2*  bes = (float2*)(sm + 37760);                // 64 float2   =   512 B
    float2*  lp  = (float2*)(sm + 38272);                // 4*64 float2 =  2048 B
    float*   ls  = (float*)(sm + 40320);                 // 4*128 float =  2048 B
    float*   ws  = (float*)(sm + 42368);                 // H*H float   = 65536 B
    int tid = threadIdx.x;

    const float4* u4 = (const float4*)u_in + (size_t)b * N * 32;
    for (int i = tid; i < C * 32; i += 512) {
        float4 v = u4[i];
        ((__half2*)ush)[2 * i]     = __floats2half2_rn(v.x, v.y);
        ((__half2*)ush)[2 * i + 1] = __floats2half2_rn(v.z, v.w);
    }
    const float4* w4 = (const float4*)wl;
    for (int i = tid; i < H * H / 4; i += 512) ((float4*)ws)[i] = w4[i];
    if (tid < 64) {
        #pragma unroll
        for (int e = 0; e < E; e++)
            wes[e * 64 + tid] = make_float2(we[e * H + 2 * tid], we[e * H + 2 * tid + 1]);
        bes[tid] = make_float2(be[2 * tid], be[2 * tid + 1]);
    }
    for (int i = tid; i < 4 * C * E; i += 512) {
        int nl = i / (C * E), rem = i % (C * E), c = rem / E, e = rem % E;
        int n = min(g * 4 + nl, N - 1);
        es[i] = edge[(((size_t)b * C + c) * N + n) * E + e];
    }
    for (int i = tid; i < 4 * C; i += 512) {
        int nl = i / C, c = i % C;
        int n = min(g * 4 + nl, N - 1);
        ps[i] = g_pres[((size_t)b * C + c) * N + n];
    }
    __syncthreads();

    int lt = tid & 127, nl = tid >> 7;
    int h2 = lt & 63, co = lt >> 6;
    int n = g * 4 + nl;
    int nc = min(n, N - 1);
    float2 bb = bes[h2];
    float lx = 0.f, ly = 0.f;
    __half2* out = (__half2*)g_pemb + ((size_t)(b * N + nc) * C) * 64 + h2;
    const float* esn = es + nl * (C * E);
    const float* psn = ps + nl * C;
    const __half2* ush2 = (const __half2*)ush;

    for (int c = co; c < C; c += 2) {
        float a0 = bb.x, a1 = bb.y;
        #pragma unroll
        for (int e = 0; e < E; e++) {
            float ev = esn[c * E + e];
            float2 w = wes[e * 64 + h2];
            a0 = fmaf(ev, w.x, a0);
            a1 = fmaf(ev, w.y, a1);
        }
        __half2 t = tanh2_fast(__floats2half2_rn(a0, a1));
        __half2 pe = __hmul2(t, __float2half2_rn(psn[c]));
        if (n < N) out[(size_t)c * 64] = pe;
        float2 pf = __half22float2(pe);
        float2 uv = __half22float2(ush2[c * 64 + h2]);
        lx = fmaf(pf.x, uv.x, lx);
        ly = fmaf(pf.y, uv.y, ly);
    }
    if (co == 1) lp[nl * 64 + h2] = make_float2(lx, ly);
    __syncthreads();
    if (co == 0) {
        float2 o = lp[nl * 64 + h2];
        ls[nl * H + 2 * h2]     = lx + o.x;
        ls[nl * H + 2 * h2 + 1] = ly + o.y;
    }
    __syncthreads();

    // GEMM epilogue: u_out[n][h] = relu(ls[n] @ wl[:,h] + bl[h] + fx[n][h])
    {
        int gn = tid >> 7, h = tid & 127;
        const float* lrow = &ls[gn * H];
        float acc0 = 0.f, acc1 = 0.f;
        #pragma unroll 8
        for (int hp = 0; hp < H; hp += 2) {
            acc0 = fmaf(lrow[hp],     ws[hp * H + h],       acc0);
            acc1 = fmaf(lrow[hp + 1], ws[(hp + 1) * H + h], acc1);
        }
        int gnode = g * 4 + gn;
        if (gnode < N) {
            float v = acc0 + acc1 + bl[h] + g_fx[((size_t)b * N + gnode) * H + h];
            u_out[((size_t)b * N + gnode) * H + h] = fmaxf(v, 0.f);
        }
    }
}

// ---------------- einsum (c-quarter): l_q[b,n,h] = sum_{c in q} pemb*u ------
// grid = B*NT*4 (1664), block 256, smem 12.8 KB -> high occupancy.
__global__ void __launch_bounds__(256) k_einsum(const float* __restrict__ u_in)
{
    int id = blockIdx.x;
    int q = id & 3, nt = (id >> 2) % NT, b = id / (4 * NT);
    float4* us4 = (float4*)smraw;              // C4*32 float4 = 12800 B
    int tid = threadIdx.x;

    const float4* u4 = (const float4*)u_in + ((size_t)b * N + q * C4) * 32;
    for (int i = tid; i < C4 * 32; i += 256) us4[i] = u4[i];
    __syncthreads();

    int lane = tid & 31, nl = tid >> 5;
    int n = nt * TN + nl;
    int nc = min(n, N - 1);
    int sub = lane >> 4, l16 = lane & 15;

    const uint4* pp = (const uint4*)g_pemb +
                      ((size_t)(b * N + nc) * C + q * C4) * 16 + l16;
    float a0 = 0.f, a1 = 0.f, a2 = 0.f, a3 = 0.f;
    float a4 = 0.f, a5 = 0.f, a6 = 0.f, a7 = 0.f;
    #pragma unroll
    for (int i = 0; i < 12; i++) {
        int c = 2 * i + sub;
        uint4 pv = pp[(size_t)c * 16];
        float4 ua = us4[c * 32 + l16 * 2];
        float4 ub = us4[c * 32 + l16 * 2 + 1];
        float2 p0 = __half22float2(*(__half2*)&pv.x);
        float2 p1 = __half22float2(*(__half2*)&pv.y);
        float2 p2 = __half22float2(*(__half2*)&pv.z);
        float2 p3 = __half22float2(*(__half2*)&pv.w);
        a0 = fmaf(p0.x, ua.x, a0); a1 = fmaf(p0.y, ua.y, a1);
        a2 = fmaf(p1.x, ua.z, a2); a3 = fmaf(p1.y, ua.w, a3);
        a4 = fmaf(p2.x, ub.x, a4); a5 = fmaf(p2.y, ub.y, a5);
        a6 = fmaf(p3.x, ub.z, a6); a7 = fmaf(p3.y, ub.w, a7);
    }
    if (sub == 0) {                            // tail c = 24
        const int c = 24;
        uint4 pv = pp[(size_t)c * 16];
        float4 ua = us4[c * 32 + l16 * 2];
        float4 ub = us4[c * 32 + l16 * 2 + 1];
        float2 p0 = __half22float2(*(__half2*)&pv.x);
        float2 p1 = __half22float2(*(__half2*)&pv.y);
        float2 p2 = __half22float2(*(__half2*)&pv.z);
        float2 p3 = __half22float2(*(__half2*)&pv.w);
        a0 = fmaf(p0.x, ua.x, a0); a1 = fmaf(p0.y, ua.y, a1);
        a2 = fmaf(p1.x, ua.z, a2); a3 = fmaf(p1.y, ua.w, a3);
        a4 = fmaf(p2.x, ub.x, a4); a5 = fmaf(p2.y, ub.y, a5);
        a6 = fmaf(p3.x, ub.z, a6); a7 = fmaf(p3.y, ub.w, a7);
    }
    a0 += __shfl_xor_sync(0xffffffffu, a0, 16);
    a1 += __shfl_xor_sync(0xffffffffu, a1, 16);
    a2 += __shfl_xor_sync(0xffffffffu, a2, 16);
    a3 += __shfl_xor_sync(0xffffffffu, a3, 16);
    a4 += __shfl_xor_sync(0xffffffffu, a4, 16);
    a5 += __shfl_xor_sync(0xffffffffu, a5, 16);
    a6 += __shfl_xor_sync(0xffffffffu, a6, 16);
    a7 += __shfl_xor_sync(0xffffffffu, a7, 16);
    if (sub == 0 && n < N) {
        float4* lo = (float4*)g_l + (((size_t)q * B + b) * NPAD + n) * 32 + l16 * 2;
        lo[0] = make_float4(a0, a1, a2, a3);
        lo[1] = make_float4(a4, a5, a6, a7);
    }
}

// ---------------- u_out = relu((sum_q l_q) @ wl + bl + fx) ------------------
// grid = B*14 (448), block 256. Thread computes 2 nodes x 2 h.
__global__ void __launch_bounds__(256) k_lgemm(const float* __restrict__ wl,
                                               const float* __restrict__ bl,
                                               float* __restrict__ u_out)
{
    int r = blockIdx.x % 14;
    int b = blockIdx.x / 14;
    int nt = r >> 1, hh = r & 1;
    int base = nt * TG;
    int hbase = hh * 64;
    float* ws = (float*)smraw;                 // 128 x 64 = 32768 B
    float* ls = (float*)smraw + 128 * 64;      // TG x 128 =  8192 B
    int tid = threadIdx.x;

    #pragma unroll
    for (int i = tid; i < 128 * 16; i += 256) {
        int hp = i >> 4, j = i & 15;
        *(float4*)&ws[hp * 64 + j * 4] = *(const float4*)&wl[hp * H + hbase + j * 4];
    }
    #pragma unroll
    for (int i = tid; i < TG * 32; i += 256) {
        int nl = i >> 5, j = i & 31;
        int n = base + nl;
        float4 v = make_float4(0.f, 0.f, 0.f, 0.f);
        if (n < N) {
            #pragma unroll
            for (int q = 0; q < 4; q++) {
                float4 x = ((const float4*)g_l)[(((size_t)q * B + b) * NPAD + n) * 32 + j];
                v.x += x.x; v.y += x.y; v.z += x.z; v.w += x.w;
            }
        }
        *(float4*)&ls[nl * 128 + j * 4] = v;
    }
    __syncthreads();

    int np = tid >> 5, th = tid & 31;          // warp = node pair
    const float* l0p = &ls[(np * 2) * 128];
    const float* l1p = &ls[(np * 2 + 1) * 128];
    float ax0 = 0.f, ay0 = 0.f, ax1 = 0.f, ay1 = 0.f;
    #pragma unroll 8
    for (int hp = 0; hp < H; hp++) {
        float2 w = *(float2*)&ws[hp * 64 + th * 2];
        float l0 = l0p[hp], l1 = l1p[hp];
        ax0 = fmaf(l0, w.x, ax0); ay0 = fmaf(l0, w.y, ay0);
        ax1 = fmaf(l1, w.x, ax1); ay1 = fmaf(l1, w.y, ay1);
    }
    int h0 = hbase + th * 2;
    float2 bb = *(const float2*)&bl[h0];
    int n0 = base + np * 2, n1 = n0 + 1;
    if (n0 < N) {
        float2 fx = *(const float2*)&g_fx[((size_t)b * N + n0) * H + h0];
        *(float2*)&u_out[((size_t)b * N + n0) * H + h0] =
            make_float2(fmaxf(ax0 + bb.x + fx.x, 0.f), fmaxf(ay0 + bb.y + fx.y, 0.f));
    }
    if (n1 < N) {
        float2 fx = *(const float2*)&g_fx[((size_t)b * N + n1) * H + h0];
        *(float2*)&u_out[((size_t)b * N + n1) * H + h0] =
            make_float2(fmaxf(ax1 + bb.x + fx.x, 0.f), fmaxf(ay1 + bb.y + fx.y, 0.f));
    }
}

// ---------------- fx2 = u5@wx2+bx2; gamma1 = relu(fx2+bl2) -> g_ub ----------
// reads g_ua (u5), writes g_fx and g_ub.
__global__ void __launch_bounds__(256) k_fx2(const float* __restrict__ wx2,
                                             const float* __restrict__ bx2,
                                             const float* __restrict__ bl2)
{
    int r = blockIdx.x % 14;
    int b = blockIdx.x / 14;
    int nt = r >> 1, hh = r & 1;
    int base = nt * TG;
    int hbase = hh * 64;
    float* ws = (float*)smraw;                 // 128 x 64
    float* ur = (float*)smraw + 128 * 64;      // TG x 128
    int tid = threadIdx.x;

    #pragma unroll
    for (int i = tid; i < 128 * 16; i += 256) {
        int hp = i >> 4, j = i & 15;
        *(float4*)&ws[hp * 64 + j * 4] = *(const float4*)&wx2[hp * H + hbase + j * 4];
    }
    #pragma unroll
    for (int i = tid; i < TG * 32; i += 256) {
        int nl = i >> 5, j = i & 31;
        int n = base + nl;
        float4 v = make_float4(0.f, 0.f, 0.f, 0.f);
        if (n < N) v = ((const float4*)g_ua)[((size_t)b * N + n) * 32 + j];
        *(float4*)&ur[nl * 128 + j * 4] = v;
    }
    __syncthreads();

    int np = tid >> 5, th = tid & 31;
    const float* u0p = &ur[(np * 2) * 128];
    const float* u1p = &ur[(np * 2 + 1) * 128];
    float ax0 = 0.f, ay0 = 0.f, ax1 = 0.f, ay1 = 0.f;
    #pragma unroll 8
    for (int hp = 0; hp < H; hp++) {
        float2 w = *(float2*)&ws[hp * 64 + th * 2];
        float u0 = u0p[hp], u1 = u1p[hp];
        ax0 = fmaf(u0, w.x, ax0); ay0 = fmaf(u0, w.y, ay0);
        ax1 = fmaf(u1, w.x, ax1); ay1 = fmaf(u1, w.y, ay1);
    }
    int h0 = hbase + th * 2;
    float2 bx = *(const float2*)&bx2[h0];
    float2 bb = *(const float2*)&bl2[h0];
    int n0 = base + np * 2, n1 = n0 + 1;
    if (n0 < N) {
        float2 fx = make_float2(ax0 + bx.x, ay0 + bx.y);
        *(float2*)&g_fx[((size_t)b * N + n0) * H + h0] = fx;
        *(float2*)&g_ub[((size_t)b * N + n0) * H + h0] =
            make_float2(fmaxf(fx.x + bb.x, 0.f), fmaxf(fx.y + bb.y, 0.f));
    }
    if (n1 < N) {
        float2 fx = make_float2(ax1 + bx.x, ay1 + bx.y);
        *(float2*)&g_fx[((size_t)b * N + n1) * H + h0] = fx;
        *(float2*)&g_ub[((size_t)b * N + n1) * H + h0] =
            make_float2(fmaxf(fx.x + bb.x, 0.f), fmaxf(fx.y + bb.y, 0.f));
    }
}

// ---------------- Q readout --------------------------------------------------
__global__ void k_reduce(const float* __restrict__ avail, const float* __restrict__ wQ,
                         const float* __restrict__ u_fin, float* __restrict__ out)
{
    int b = blockIdx.x;
    int h = threadIdx.x;
    float s = 0.f;
    for (int n = 0; n < N; n++)
        s = fmaf(u_fin[(b * N + n) * H + h], avail[b * N + n], s);
    s *= wQ[h];
    __shared__ float red[H];
    red[h] = s;
    __syncthreads();
    for (int s2 = 64; s2 > 0; s2 >>= 1) {
        if (h < s2) red[h] += red[h + s2];
        __syncthreads();
    }
    if (h == 0) out[b] = red[0];
}

// ---------------- launch -----------------------------------------------------
extern "C" void kernel_launch(void* const* d_in, const int* in_sizes, int n_in,
                              void* d_out, int out_size)
{
    const float* ap    = (const float*)d_in[0];
    const float* act   = (const float*)d_in[1];
    const float* xa    = (const float*)d_in[2];
    const float* xb    = (const float*)d_in[3];
    const float* coord = (const float*)d_in[4];
    const float* edge  = (const float*)d_in[5];
    const float* avail = (const float*)d_in[6];
    const float* w1p   = (const float*)d_in[7];
    const float* b1p   = (const float*)d_in[8];
    const float* w2p   = (const float*)d_in[9];
    const float* b2p   = (const float*)d_in[10];
    const float* wx1   = (const float*)d_in[11];
    const float* bx1   = (const float*)d_in[12];
    const float* we1   = (const float*)d_in[13];
    const float* be1   = (const float*)d_in[14];
    const float* wl1   = (const float*)d_in[15];
    const float* bl1   = (const float*)d_in[16];
    const float* wx2   = (const float*)d_in[17];
    const float* bx2   = (const float*)d_in[18];
    const float* we2   = (const float*)d_in[19];
    const float* be2   = (const float*)d_in[20];
    const float* wl2   = (const float*)d_in[21];
    const float* bl2   = (const float*)d_in[22];
    const float* wQ    = (const float*)d_in[23];
    float* out = (float*)d_out;

    float* ua; cudaGetSymbolAddress((void**)&ua, g_ua);
    float* ub; cudaGetSymbolAddress((void**)&ub, g_ub);

    const int fu_smem = 42368 + 65536;               // 107904 B
    const int es_smem = C4 * 32 * 16;                // 12800 B
    const int gm_smem = (128 * 64 + TG * 128) * 4;   // 40960 B
    cudaFuncSetAttribute(k_pemb_fused, cudaFuncAttributeMaxDynamicSharedMemorySize, fu_smem);
    cudaFuncSetAttribute(k_einsum, cudaFuncAttributeMaxDynamicSharedMemorySize, es_smem);
    cudaFuncSetAttribute(k_lgemm,  cudaFuncAttributeMaxDynamicSharedMemorySize, gm_smem);
    cudaFuncSetAttribute(k_fx2,    cudaFuncAttributeMaxDynamicSharedMemorySize, gm_smem);

    k_features<<<B * N, H>>>(ap, act, xa, xb, coord, avail, wx1, bx1, bl1);
    k_presence<<<B * C, H>>>(edge, avail, w1p, b1p, w2p, b2p);

    // round 1: u1=features(ua); fused builds pemb1 + u2 (ub); 3 einsum+gemm
    k_pemb_fused<<<B * 26, 512, fu_smem>>>(edge, we1, be1, wl1, bl1, ua, ub);
    k_einsum<<<B * NT * 4, 256, es_smem>>>(ub);
    k_lgemm<<<B * 14, 256, gm_smem>>>(wl1, bl1, ua);   // u3
    k_einsum<<<B * NT * 4, 256, es_smem>>>(ua);
    k_lgemm<<<B * 14, 256, gm_smem>>>(wl1, bl1, ub);   // u4
    k_einsum<<<B * NT * 4, 256, es_smem>>>(ub);
    k_lgemm<<<B * 14, 256, gm_smem>>>(wl1, bl1, ua);   // u5

    // round 2: fx2 from u5 (ua) -> gamma1 (ub); fused builds pemb2 + gamma2 (ua)
    k_fx2<<<B * 14, 256, gm_smem>>>(wx2, bx2, bl2);
    k_pemb_fused<<<B * 26, 512, fu_smem>>>(edge, we2, be2, wl2, bl2, ub, ua);
    k_einsum<<<B * NT * 4, 256, es_smem>>>(ua);
    k_lgemm<<<B * 14, 256, gm_smem>>>(wl2, bl2, ub);   // g3
    k_einsum<<<B * NT * 4, 256, es_smem>>>(ub);
    k_lgemm<<<B * 14, 256, gm_smem>>>(wl2, bl2, ua);   // g4
    k_einsum<<<B * NT * 4, 256, es_smem>>>(ua);
    k_lgemm<<<B * 14, 256, gm_smem>>>(wl2, bl2, ub);   // g5

    k_reduce<<<B, H>>>(avail, wQ, ub, out);
}

// round 17
// speedup vs baseline: 1.6745x; 1.6745x over previous
#include <cuda_runtime.h>
#include <cuda_fp16.h>

#define B 32
#define R 5
#define C 100
#define C4 25     // c-quarter
#define N 101
#define NPAD 104
#define H 128
#define E 5
#define F 13      // 8 + R
#define TN 8      // nodes per einsum tile
#define NT 13     // ceil(N / TN)
#define TG 16     // nodes per gemm tile

// ---------------- scratch (device globals; no allocations allowed) ----------
__device__ __half g_pemb[(size_t)B * N * C * H];       // 82.7 MB, fp16
__device__ float  g_pres[(size_t)B * C * N];           // presence [B,C,N]
__device__ float  g_fx  [(size_t)B * N * H];           // fx1 then fx2
__device__ float  g_ua  [(size_t)B * N * H];           // message-passing state
__device__ float  g_ub  [(size_t)B * N * H];           // fx2 output state
__device__ float  g_l   [4 * (size_t)B * NPAD * H];    // einsum partials (4 c-quarters)

extern __shared__ char smraw[];

__device__ __forceinline__ __half2 tanh2_fast(__half2 x) {
    unsigned xi = *(unsigned*)&x, yi;
    asm("tanh.approx.f16x2 %0, %1;" : "=r"(yi) : "r"(xi));
    return *(__half2*)&yi;
}

// ---------------- features: x -> fx1, u = relu(fx1 + bl1) -------------------
__global__ void k_features(const float* __restrict__ ap, const float* __restrict__ act,
                           const float* __restrict__ xa, const float* __restrict__ xb,
                           const float* __restrict__ coord, const float* __restrict__ avail,
                           const float* __restrict__ wx1, const float* __restrict__ bx1,
                           const float* __restrict__ bl1)
{
    int b = blockIdx.x / N, n = blockIdx.x % N;
    __shared__ float xs[F];
    int tid = threadIdx.x;
    if (tid < 5) {
        float s = 0.f;
        #pragma unroll
        for (int r = 0; r < R; r++) {
            int idx = (b * R + r) * N + n;
            float a = ap[idx] + act[idx];
            s = fmaf(a, xa[idx * R + tid], s);
        }
        xs[tid] = s;
    } else if (tid < 10) {
        xs[tid] = xb[(b * N + n) * 5 + tid - 5];
    } else if (tid < 12) {
        xs[tid] = coord[(b * N + n) * 2 + tid - 10];
    } else if (tid == 12) {
        xs[12] = avail[b * N + n];
    }
    __syncthreads();
    int h = tid;
    float acc = bx1[h];
    #pragma unroll
    for (int k = 0; k < F; k++) acc = fmaf(xs[k], wx1[k * H + h], acc);
    int o = (b * N + n) * H + h;
    g_fx[o] = acc;
    g_ua[o] = fmaxf(acc + bl1[h], 0.f);
}

// ---------------- presence head: softmax over n per (b,c) -------------------
__global__ void k_presence(const float* __restrict__ edge, const float* __restrict__ avail,
                           const float* __restrict__ w1p, const float* __restrict__ b1p,
                           const float* __restrict__ w2p, const float* __restrict__ b2p)
{
    int b = blockIdx.x / C, c = blockIdx.x % C;
    __shared__ float w1s[E * H], b1s[H], w2s[H], lg[N], red[H];
    int tid = threadIdx.x;
    for (int i = tid; i < E * H; i += H) w1s[i] = w1p[i];
    b1s[tid] = b1p[tid];
    w2s[tid] = w2p[tid];
    __syncthreads();

    float lgv = -3.4e38f;
    if (tid < N) {
        int n = tid;
        const float* e5 = edge + ((size_t)(b * C + c) * N + n) * E;
        float e0 = e5[0], e1 = e5[1], e2 = e5[2], e3 = e5[3], e4 = e5[4];
        float s = 0.f;
        #pragma unroll 4
        for (int h = 0; h < H; h++) {
            float a = b1s[h];
            a = fmaf(e0, w1s[h], a);
            a = fmaf(e1, w1s[H + h], a);
            a = fmaf(e2, w1s[2 * H + h], a);
            a = fmaf(e3, w1s[3 * H + h], a);
            a = fmaf(e4, w1s[4 * H + h], a);
            s = fmaf(fmaxf(a, 0.f), w2s[h], s);
        }
        s = s + b2p[0];                  // TAU = 1
        float m = avail[b * N + n];
        if (n == c || n == N - 1) m = 0.f;
        lgv = s * m - (1.f - m) * 1e10f;
        lg[n] = lgv;
    }
    red[tid] = lgv;
    __syncthreads();
    for (int s2 = 64; s2 > 0; s2 >>= 1) {
        if (tid < s2) red[tid] = fmaxf(red[tid], red[tid + s2]);
        __syncthreads();
    }
    float mx = red[0];
    __syncthreads();
    float p = 0.f;
    if (tid < N) p = __expf(lg[tid] - mx);
    red[tid] = p;
    __syncthreads();
    for (int s2 = 64; s2 > 0; s2 >>= 1) {
        if (tid < s2) red[tid] += red[tid + s2];
        __syncthreads();
    }
    float inv = 1.f / red[0];
    if (tid < N) {
        float availc = avail[b * N + c];
        g_pres[(size_t)(b * C + c) * N + tid] = availc * p * inv;
    }
}

// ---------------- fused: build pemb (fp16) AND first einsum sweep -----------
// grid = B*26 (4 nodes per CTA), block 512. Writes l into quarter 0 of g_l.
__global__ void k_pemb_fused(const float* __restrict__ edge, const float* __restrict__ we,
                             const float* __restrict__ be, const float* __restrict__ u_in)
{
    int b = blockIdx.x / 26, g = blockIdx.x % 26;
    char* sm = smraw;
    float2* us  = (float2*)sm;                           // 100*64 float2 = 51200 B
    float*  es  = (float*)(sm + 51200);                  // 4*100*5      =  8000 B
    float*  ps  = (float*)(sm + 59200);                  // 4*100        =  1600 B
    float2* wes = (float2*)(sm + 60800);                 // 5*64 float2  =  2560 B
    float2* bes = (float2*)(sm + 63360);                 // 64 float2    =   512 B
    float2* ls  = (float2*)(sm + 63872);                 // 4*64 float2  =  2048 B
    int tid = threadIdx.x;

    const float4* u4 = (const float4*)u_in + (size_t)b * N * 32;
    float4* us4p = (float4*)us;
    for (int i = tid; i < C * 32; i += 512) us4p[i] = u4[i];
    if (tid < 64) {
        #pragma unroll
        for (int e = 0; e < E; e++)
            wes[e * 64 + tid] = make_float2(we[e * H + 2 * tid], we[e * H + 2 * tid + 1]);
        bes[tid] = make_float2(be[2 * tid], be[2 * tid + 1]);
    }
    for (int i = tid; i < 4 * C * E; i += 512) {
        int nl = i / (C * E), rem = i % (C * E), c = rem / E, e = rem % E;
        int n = min(g * 4 + nl, N - 1);
        es[i] = edge[(((size_t)b * C + c) * N + n) * E + e];
    }
    for (int i = tid; i < 4 * C; i += 512) {
        int nl = i / C, c = i % C;
        int n = min(g * 4 + nl, N - 1);
        ps[i] = g_pres[((size_t)b * C + c) * N + n];
    }
    __syncthreads();

    int lt = tid & 127, nl = tid >> 7;
    int h2 = lt & 63, co = lt >> 6;
    int n = g * 4 + nl;
    int nc = min(n, N - 1);
    float2 bb = bes[h2];
    float lx = 0.f, ly = 0.f;
    __half2* out = (__half2*)g_pemb + ((size_t)(b * N + nc) * C) * 64 + h2;
    const float* esn = es + nl * (C * E);
    const float* psn = ps + nl * C;

    for (int c = co; c < C; c += 2) {
        float a0 = bb.x, a1 = bb.y;
        #pragma unroll
        for (int e = 0; e < E; e++) {
            float ev = esn[c * E + e];
            float2 w = wes[e * 64 + h2];
            a0 = fmaf(ev, w.x, a0);
            a1 = fmaf(ev, w.y, a1);
        }
        __half2 t = tanh2_fast(__floats2half2_rn(a0, a1));
        __half2 pe = __hmul2(t, __float2half2_rn(psn[c]));
        if (n < N) out[(size_t)c * 64] = pe;
        float2 pf = __half22float2(pe);
        float2 uv = us[c * 64 + h2];
        lx = fmaf(pf.x, uv.x, lx);
        ly = fmaf(pf.y, uv.y, ly);
    }
    if (co == 1) ls[nl * 64 + h2] = make_float2(lx, ly);
    __syncthreads();
    if (co == 0 && n < N) {
        float2 o = ls[nl * 64 + h2];
        ((float2*)g_l)[((size_t)b * NPAD + n) * 64 + h2] =
            make_float2(lx + o.x, ly + o.y);
    }
}

// ---------------- einsum (c-quarter): l_q[b,n,h] = sum_{c in q} pemb*u ------
// grid = B*NT*4 (1664), block 256, smem 6.4 KB (u in fp16 -> half LDS traffic).
__global__ void __launch_bounds__(256) k_einsum()
{
    int id = blockIdx.x;
    int q = id & 3, nt = (id >> 2) % NT, b = id / (4 * NT);
    __half2* uh = (__half2*)smraw;             // C4*64 half2 = 6400 B
    int tid = threadIdx.x;

    const float2* u2 = (const float2*)g_ua + ((size_t)b * N + q * C4) * 64;
    for (int i = tid; i < C4 * 64; i += 256) uh[i] = __float22half2_rn(u2[i]);
    __syncthreads();

    int lane = tid & 31, nl = tid >> 5;
    int n = nt * TN + nl;
    int nc = min(n, N - 1);
    int sub = lane >> 4, l16 = lane & 15;

    const uint4* pp = (const uint4*)g_pemb +
                      ((size_t)(b * N + nc) * C + q * C4) * 16 + l16;
    const uint4* uu = (const uint4*)uh + l16;
    float a0 = 0.f, a1 = 0.f, a2 = 0.f, a3 = 0.f;
    float a4 = 0.f, a5 = 0.f, a6 = 0.f, a7 = 0.f;
    #pragma unroll
    for (int i = 0; i < 12; i++) {
        int c = 2 * i + sub;
        uint4 pv = pp[(size_t)c * 16];
        uint4 uv = uu[c * 16];
        float2 p0 = __half22float2(*(__half2*)&pv.x);
        float2 p1 = __half22float2(*(__half2*)&pv.y);
        float2 p2 = __half22float2(*(__half2*)&pv.z);
        float2 p3 = __half22float2(*(__half2*)&pv.w);
        float2 q0 = __half22float2(*(__half2*)&uv.x);
        float2 q1 = __half22float2(*(__half2*)&uv.y);
        float2 q2 = __half22float2(*(__half2*)&uv.z);
        float2 q3 = __half22float2(*(__half2*)&uv.w);
        a0 = fmaf(p0.x, q0.x, a0); a1 = fmaf(p0.y, q0.y, a1);
        a2 = fmaf(p1.x, q1.x, a2); a3 = fmaf(p1.y, q1.y, a3);
        a4 = fmaf(p2.x, q2.x, a4); a5 = fmaf(p2.y, q2.y, a5);
        a6 = fmaf(p3.x, q3.x, a6); a7 = fmaf(p3.y, q3.y, a7);
    }
    if (sub == 0) {                            // tail c = 24
        const int c = 24;
        uint4 pv = pp[(size_t)c * 16];
        uint4 uv = uu[c * 16];
        float2 p0 = __half22float2(*(__half2*)&pv.x);
        float2 p1 = __half22float2(*(__half2*)&pv.y);
        float2 p2 = __half22float2(*(__half2*)&pv.z);
        float2 p3 = __half22float2(*(__half2*)&pv.w);
        float2 q0 = __half22float2(*(__half2*)&uv.x);
        float2 q1 = __half22float2(*(__half2*)&uv.y);
        float2 q2 = __half22float2(*(__half2*)&uv.z);
        float2 q3 = __half22float2(*(__half2*)&uv.w);
        a0 = fmaf(p0.x, q0.x, a0); a1 = fmaf(p0.y, q0.y, a1);
        a2 = fmaf(p1.x, q1.x, a2); a3 = fmaf(p1.y, q1.y, a3);
        a4 = fmaf(p2.x, q2.x, a4); a5 = fmaf(p2.y, q2.y, a5);
        a6 = fmaf(p3.x, q3.x, a6); a7 = fmaf(p3.y, q3.y, a7);
    }
    a0 += __shfl_xor_sync(0xffffffffu, a0, 16);
    a1 += __shfl_xor_sync(0xffffffffu, a1, 16);
    a2 += __shfl_xor_sync(0xffffffffu, a2, 16);
    a3 += __shfl_xor_sync(0xffffffffu, a3, 16);
    a4 += __shfl_xor_sync(0xffffffffu, a4, 16);
    a5 += __shfl_xor_sync(0xffffffffu, a5, 16);
    a6 += __shfl_xor_sync(0xffffffffu, a6, 16);
    a7 += __shfl_xor_sync(0xffffffffu, a7, 16);
    if (sub == 0 && n < N) {
        float4* lo = (float4*)g_l + (((size_t)q * B + b) * NPAD + n) * 32 + l16 * 2;
        lo[0] = make_float4(a0, a1, a2, a3);
        lo[1] = make_float4(a4, a5, a6, a7);
    }
}

// ---------------- u = relu((sum_q l_q) @ wl + bl + fx) ----------------------
// grid = B*14 (448), block 256. Thread computes 2 nodes x 2 h.
template<int NPARTS>
__global__ void __launch_bounds__(256) k_lgemm(const float* __restrict__ wl,
                                               const float* __restrict__ bl)
{
    int r = blockIdx.x % 14;
    int b = blockIdx.x / 14;
    int nt = r >> 1, hh = r & 1;
    int base = nt * TG;
    int hbase = hh * 64;
    float* ws = (float*)smraw;                 // 128 x 64 = 32768 B
    float* ls = (float*)smraw + 128 * 64;      // TG x 128 =  8192 B
    int tid = threadIdx.x;

    #pragma unroll
    for (int i = tid; i < 128 * 16; i += 256) {
        int hp = i >> 4, j = i & 15;
        *(float4*)&ws[hp * 64 + j * 4] = *(const float4*)&wl[hp * H + hbase + j * 4];
    }
    #pragma unroll
    for (int i = tid; i < TG * 32; i += 256) {
        int nl = i >> 5, j = i & 31;
        int n = base + nl;
        float4 v = make_float4(0.f, 0.f, 0.f, 0.f);
        if (n < N) {
            #pragma unroll
            for (int q = 0; q < NPARTS; q++) {
                float4 x = ((const float4*)g_l)[(((size_t)q * B + b) * NPAD + n) * 32 + j];
                v.x += x.x; v.y += x.y; v.z += x.z; v.w += x.w;
            }
        }
        *(float4*)&ls[nl * 128 + j * 4] = v;
    }
    __syncthreads();

    int np = tid >> 5, th = tid & 31;          // warp = node pair
    const float* l0p = &ls[(np * 2) * 128];
    const float* l1p = &ls[(np * 2 + 1) * 128];
    float ax0 = 0.f, ay0 = 0.f, ax1 = 0.f, ay1 = 0.f;
    #pragma unroll 8
    for (int hp = 0; hp < H; hp++) {
        float2 w = *(float2*)&ws[hp * 64 + th * 2];
        float l0 = l0p[hp], l1 = l1p[hp];
        ax0 = fmaf(l0, w.x, ax0); ay0 = fmaf(l0, w.y, ay0);
        ax1 = fmaf(l1, w.x, ax1); ay1 = fmaf(l1, w.y, ay1);
    }
    int h0 = hbase + th * 2;
    float2 bb = *(const float2*)&bl[h0];
    int n0 = base + np * 2, n1 = n0 + 1;
    if (n0 < N) {
        float2 fx = *(const float2*)&g_fx[((size_t)b * N + n0) * H + h0];
        *(float2*)&g_ua[((size_t)b * N + n0) * H + h0] =
            make_float2(fmaxf(ax0 + bb.x + fx.x, 0.f), fmaxf(ay0 + bb.y + fx.y, 0.f));
    }
    if (n1 < N) {
        float2 fx = *(const float2*)&g_fx[((size_t)b * N + n1) * H + h0];
        *(float2*)&g_ua[((size_t)b * N + n1) * H + h0] =
            make_float2(fmaxf(ax1 + bb.x + fx.x, 0.f), fmaxf(ay1 + bb.y + fx.y, 0.f));
    }
}

// ---------------- fx2 = u@wx2+bx2; gamma_init = relu(fx2+bl2) -> g_ub -------
__global__ void __launch_bounds__(256) k_fx2(const float* __restrict__ wx2,
                                             const float* __restrict__ bx2,
                                             const float* __restrict__ bl2)
{
    int r = blockIdx.x % 14;
    int b = blockIdx.x / 14;
    int nt = r >> 1, hh = r & 1;
    int base = nt * TG;
    int hbase = hh * 64;
    float* ws = (float*)smraw;                 // 128 x 64
    float* ur = (float*)smraw + 128 * 64;      // TG x 128
    int tid = threadIdx.x;

    #pragma unroll
    for (int i = tid; i < 128 * 16; i += 256) {
        int hp = i >> 4, j = i & 15;
        *(float4*)&ws[hp * 64 + j * 4] = *(const float4*)&wx2[hp * H + hbase + j * 4];
    }
    #pragma unroll
    for (int i = tid; i < TG * 32; i += 256) {
        int nl = i >> 5, j = i & 31;
        int n = base + nl;
        float4 v = make_float4(0.f, 0.f, 0.f, 0.f);
        if (n < N) v = ((const float4*)g_ua)[((size_t)b * N + n) * 32 + j];
        *(float4*)&ur[nl * 128 + j * 4] = v;
    }
    __syncthreads();

    int np = tid >> 5, th = tid & 31;
    const float* u0p = &ur[(np * 2) * 128];
    const float* u1p = &ur[(np * 2 + 1) * 128];
    float ax0 = 0.f, ay0 = 0.f, ax1 = 0.f, ay1 = 0.f;
    #pragma unroll 8
    for (int hp = 0; hp < H; hp++) {
        float2 w = *(float2*)&ws[hp * 64 + th * 2];
        float u0 = u0p[hp], u1 = u1p[hp];
        ax0 = fmaf(u0, w.x, ax0); ay0 = fmaf(u0, w.y, ay0);
        ax1 = fmaf(u1, w.x, ax1); ay1 = fmaf(u1, w.y, ay1);
    }
    int h0 = hbase + th * 2;
    float2 bx = *(const float2*)&bx2[h0];
    float2 bb = *(const float2*)&bl2[h0];
    int n0 = base + np * 2, n1 = n0 + 1;
    if (n0 < N) {
        float2 fx = make_float2(ax0 + bx.x, ay0 + bx.y);
        *(float2*)&g_fx[((size_t)b * N + n0) * H + h0] = fx;
        *(float2*)&g_ub[((size_t)b * N + n0) * H + h0] =
            make_float2(fmaxf(fx.x + bb.x, 0.f), fmaxf(fx.y + bb.y, 0.f));
    }
    if (n1 < N) {
        float2 fx = make_float2(ax1 + bx.x, ay1 + bx.y);
        *(float2*)&g_fx[((size_t)b * N + n1) * H + h0] = fx;
        *(float2*)&g_ub[((size_t)b * N + n1) * H + h0] =
            make_float2(fmaxf(fx.x + bb.x, 0.f), fmaxf(fx.y + bb.y, 0.f));
    }
}

// ---------------- Q readout --------------------------------------------------
__global__ void k_reduce(const float* __restrict__ avail, const float* __restrict__ wQ,
                         float* __restrict__ out)
{
    int b = blockIdx.x;
    int h = threadIdx.x;
    float s = 0.f;
    for (int n = 0; n < N; n++)
        s = fmaf(g_ua[(b * N + n) * H + h], avail[b * N + n], s);
    s *= wQ[h];
    __shared__ float red[H];
    red[h] = s;
    __syncthreads();
    for (int s2 = 64; s2 > 0; s2 >>= 1) {
        if (h < s2) red[h] += red[h + s2];
        __syncthreads();
    }
    if (h == 0) out[b] = red[0];
}

// ---------------- launch -----------------------------------------------------
extern "C" void kernel_launch(void* const* d_in, const int* in_sizes, int n_in,
                              void* d_out, int out_size)
{
    const float* ap    = (const float*)d_in[0];
    const float* act   = (const float*)d_in[1];
    const float* xa    = (const float*)d_in[2];
    const float* xb    = (const float*)d_in[3];
    const float* coord = (const float*)d_in[4];
    const float* edge  = (const float*)d_in[5];
    const float* avail = (const float*)d_in[6];
    const float* w1p   = (const float*)d_in[7];
    const float* b1p   = (const float*)d_in[8];
    const float* w2p   = (const float*)d_in[9];
    const float* b2p   = (const float*)d_in[10];
    const float* wx1   = (const float*)d_in[11];
    const float* bx1   = (const float*)d_in[12];
    const float* we1   = (const float*)d_in[13];
    const float* be1   = (const float*)d_in[14];
    const float* wl1   = (const float*)d_in[15];
    const float* bl1   = (const float*)d_in[16];
    const float* wx2   = (const float*)d_in[17];
    const float* bx2   = (const float*)d_in[18];
    const float* we2   = (const float*)d_in[19];
    const float* be2   = (const float*)d_in[20];
    const float* wl2   = (const float*)d_in[21];
    const float* bl2   = (const float*)d_in[22];
    const float* wQ    = (const float*)d_in[23];
    float* out = (float*)d_out;

    float* g_ua_ptr; cudaGetSymbolAddress((void**)&g_ua_ptr, g_ua);
    float* g_ub_ptr; cudaGetSymbolAddress((void**)&g_ub_ptr, g_ub);

    const int fu_smem = 65920;                       // k_pemb_fused
    const int es_smem = C4 * 64 * 4;                 // 6400 B (fp16 u)
    const int gm_smem = (128 * 64 + TG * 128) * 4;   // 40960 B
    cudaFuncSetAttribute(k_pemb_fused, cudaFuncAttributeMaxDynamicSharedMemorySize, fu_smem);
    cudaFuncSetAttribute(k_einsum, cudaFuncAttributeMaxDynamicSharedMemorySize, es_smem);
    cudaFuncSetAttribute(k_lgemm<1>, cudaFuncAttributeMaxDynamicSharedMemorySize, gm_smem);
    cudaFuncSetAttribute(k_lgemm<4>, cudaFuncAttributeMaxDynamicSharedMemorySize, gm_smem);
    cudaFuncSetAttribute(k_fx2,      cudaFuncAttributeMaxDynamicSharedMemorySize, gm_smem);

    k_features<<<B * N, H>>>(ap, act, xa, xb, coord, avail, wx1, bx1, bl1);
    k_presence<<<B * C, H>>>(edge, avail, w1p, b1p, w2p, b2p);

    // round 1: iter1 folded into k_features; iter2 fused with pemb build
    k_pemb_fused<<<B * 26, 512, fu_smem>>>(edge, we1, be1, g_ua_ptr);
    k_lgemm<1><<<B * 14, 256, gm_smem>>>(wl1, bl1);
    for (int t = 0; t < 3; t++) {
        k_einsum<<<B * NT * 4, 256, es_smem>>>();
        k_lgemm<4><<<B * 14, 256, gm_smem>>>(wl1, bl1);
    }

    // round 2
    k_fx2<<<B * 14, 256, gm_smem>>>(wx2, bx2, bl2);
    k_pemb_fused<<<B * 26, 512, fu_smem>>>(edge, we2, be2, g_ub_ptr);
    k_lgemm<1><<<B * 14, 256, gm_smem>>>(wl2, bl2);
    for (int t = 0; t < 3; t++) {
        k_einsum<<<B * NT * 4, 256, es_smem>>>();
        k_lgemm<4><<<B * 14, 256, gm_smem>>>(wl2, bl2);
    }

    k_reduce<<<B, H>>>(avail, wQ, out);
}